// round 11
// baseline (speedup 1.0000x reference)
#include <cuda_runtime.h>
#include <cuda_bf16.h>
#include <cstdint>
#include <cstddef>
#include <math.h>

// Problem constants (fixed dataset)
#define B_   2
#define E_   160000
#define N_   10000
#define FIN_ 24
#define D_   128
#define P2E_ (2 * E_)
#define NTILE_ (E_ / 32)   // 5000

// ---------------- scratch (static __device__, no allocations) ----------------
__device__ float g_emb[(size_t)B_ * E_ * D_];     // edge embeddings [B][E][128] fp32
__device__ __nv_bfloat16 g_embh[(size_t)B_ * E_ * D_]; // bf16 mirror for MP gather
__device__ float g_edot[2][(size_t)B_ * E_];      // per-layer e_pair . watt[128:256]
__device__ float g_nodeA[(size_t)B_ * N_ * D_];   // node emb after layer 1
__device__ float g_nodeB[(size_t)B_ * N_ * D_];   // node emb after layer 2
__device__ int   g_cnt[N_];
__device__ int   g_cur[N_];
__device__ int   g_off[N_ + 1];
__device__ int   g_adj[P2E_];
// bf16 packed weights, m16n8k16 B-fragment order, hi|lo INTERLEAVED per (n,tig):
//   group g=(s*N+n)*4+t holds 8 bf16: [hi j=0..3 | lo j=0..3], k = s*16+2t+(j&1)+((j>>1)<<3)
__device__ __align__(16) __nv_bfloat16 g_w1p[384 * 256 * 2];
__device__ __align__(16) __nv_bfloat16 g_w2p[256 * 128 * 2];
__device__ __align__(16) __nv_bfloat16 g_ew2p[128 * 128 * 2];
__device__ __align__(16) __nv_bfloat16 g_ew1p[32 * 128 * 2];   // enc W1, k padded 24->32

// ---------------- helpers ----------------
__device__ __forceinline__ float gelu_f(float x) {
    return 0.5f * x * (1.0f + erff(x * 0.70710678118654752f));
}
__device__ __forceinline__ float wsum(float v) {
#pragma unroll
    for (int o = 16; o; o >>= 1) v += __shfl_xor_sync(0xffffffffu, v, o);
    return v;
}
__device__ __forceinline__ float wmax(float v) {
#pragma unroll
    for (int o = 16; o; o >>= 1) v = fmaxf(v, __shfl_xor_sync(0xffffffffu, v, o));
    return v;
}
__device__ __forceinline__ uint32_t s2u(const void* p) {
    return (uint32_t)__cvta_generic_to_shared(p);
}
__device__ __forceinline__ void cpa16(uint32_t dst, const void* src) {
    asm volatile("cp.async.cg.shared.global [%0], [%1], 16;" :: "r"(dst), "l"(src));
}
__device__ __forceinline__ void cpa_commit() {
    asm volatile("cp.async.commit_group;" ::: "memory");
}
__device__ __forceinline__ void cpa_wait0() {
    asm volatile("cp.async.wait_group 0;" ::: "memory");
}
__device__ __forceinline__ void cpa_wait1() {
    asm volatile("cp.async.wait_group 1;" ::: "memory");
}
__device__ __forceinline__ void cpa_wait2() {
    asm volatile("cp.async.wait_group 2;" ::: "memory");
}
#define LDMX4(r, addr) \
    asm volatile("ldmatrix.sync.aligned.m8n8.x4.shared.b16 {%0,%1,%2,%3}, [%4];" \
        : "=r"((r)[0]), "=r"((r)[1]), "=r"((r)[2]), "=r"((r)[3]) : "r"(addr))

__device__ __forceinline__ void mma_bf16(float* c, const uint32_t* a,
                                         uint32_t b0, uint32_t b1) {
    asm volatile(
        "mma.sync.aligned.m16n8k16.row.col.f32.bf16.bf16.f32 "
        "{%0,%1,%2,%3},{%4,%5,%6,%7},{%8,%9},{%0,%1,%2,%3};"
        : "+f"(c[0]), "+f"(c[1]), "+f"(c[2]), "+f"(c[3])
        : "r"(a[0]), "r"(a[1]), "r"(a[2]), "r"(a[3]), "r"(b0), "r"(b1));
}

// ---------------- weight pack prep (interleaved hi|lo fragment groups) ----------------
__device__ __forceinline__ void pack_group(__nv_bfloat16* dst, const float* src,
                                           int N, int gi, int Kmax) {
    int t = gi & 3;
    int n = (gi >> 2) % N;
    int s = gi / (4 * N);
#pragma unroll
    for (int j = 0; j < 4; j++) {
        int k = s * 16 + 2 * t + (j & 1) + ((j >> 1) << 3);
        float x = (k < Kmax) ? src[k * N + n] : 0.f;
        __nv_bfloat16 h = __float2bfloat16_rn(x);
        dst[gi * 8 + j]     = h;
        dst[gi * 8 + 4 + j] = __float2bfloat16_rn(x - __bfloat162float(h));
    }
}

__global__ void pack_weights_kernel(const float* __restrict__ w1,
                                    const float* __restrict__ w2,
                                    const float* __restrict__ ew2,
                                    const float* __restrict__ ew1) {
    int gi = blockIdx.x * blockDim.x + threadIdx.x;
    if (gi < N_) g_cnt[gi] = 0;   // fused zero_cnt
    if (gi < 24576)       pack_group(g_w1p, w1, 256, gi, 384);            // dec W1 384x256
    else if (gi < 32768)  pack_group(g_w2p, w2, 128, gi - 24576, 256);    // dec W2 256x128
    else if (gi < 36864)  pack_group(g_ew2p, ew2, 128, gi - 32768, 128);  // enc W2 128x128
    else if (gi < 37888)  pack_group(g_ew1p, ew1, 128, gi - 36864, 24);   // enc W1 24x128 (pad 32)
}

// ---------------- CSR build ----------------
__global__ void count_kernel(const int* __restrict__ src, const int* __restrict__ dst) {
    int idx = blockIdx.x * blockDim.x + threadIdx.x;
    if (idx >= P2E_) return;
    int node = (idx < E_) ? src[idx] : dst[idx - E_];
    atomicAdd(&g_cnt[node], 1);
}

__global__ void scan_kernel() {
    __shared__ int ss[1024];
    int t = threadIdx.x;
    int base = t * 10;                  // 1024*10 >= N_
    int s = 0;
#pragma unroll
    for (int i = 0; i < 10; i++) {
        int idx = base + i;
        if (idx < N_) s += g_cnt[idx];
    }
    ss[t] = s;
    __syncthreads();
    for (int off = 1; off < 1024; off <<= 1) {
        int v = (t >= off) ? ss[t - off] : 0;
        __syncthreads();
        ss[t] += v;
        __syncthreads();
    }
    int run = (t > 0) ? ss[t - 1] : 0;
#pragma unroll
    for (int i = 0; i < 10; i++) {
        int idx = base + i;
        if (idx < N_) {
            g_off[idx] = run;
            run += g_cnt[idx];
            g_cur[idx] = 0;
        }
    }
    if (t == 1023) g_off[N_] = ss[1023];
}

__global__ void fill_kernel(const int* __restrict__ src, const int* __restrict__ dst) {
    int idx = blockIdx.x * blockDim.x + threadIdx.x;
    if (idx >= P2E_) return;
    int node = (idx < E_) ? src[idx] : dst[idx - E_];
    int e    = (idx < E_) ? idx : idx - E_;
    int pos = g_off[node] + atomicAdd(&g_cur[node], 1);
    g_adj[pos] = e;
}

// ---------------- persistent fused edge encoder (both GEMMs tensorized) ----------------
#define ENC_SMEM_BYTES 111872
__global__ void __launch_bounds__(256, 2) encoder_kernel(
    const float* __restrict__ xin,
    const float* __restrict__ b1,
    const float* __restrict__ g1, const float* __restrict__ be1,
    const float* __restrict__ b2,
    const float* __restrict__ g2, const float* __restrict__ be2,
    const float* __restrict__ watt1, const float* __restrict__ watt2)
{
    extern __shared__ char smraw[];
    float* xs = (float*)(smraw);             // two 768-float buffers
    __nv_bfloat16* eW1P = (__nv_bfloat16*)(smraw + 6144);
    __nv_bfloat16* eW2P = (__nv_bfloat16*)(smraw + 22528);
    __nv_bfloat16* aHi  = (__nv_bfloat16*)(smraw + 88064);
    __nv_bfloat16* aLo  = (__nv_bfloat16*)(smraw + 96768);
    __nv_bfloat16* xHi  = aHi;   // alias: x frags dead before gelu writes land
    __nv_bfloat16* xLo  = aLo;
    float* vb1  = (float*)(smraw + 105472);
    float* vg1  = (float*)(smraw + 105984);
    float* vbe1 = (float*)(smraw + 106496);
    float* vb2  = (float*)(smraw + 107008);
    float* vg2  = (float*)(smraw + 107520);
    float* vbe2 = (float*)(smraw + 108032);
    float* we1  = (float*)(smraw + 108544);
    float* we2  = (float*)(smraw + 109056);
    float* red  = (float*)(smraw + 109568);
    float* mub  = (float*)(smraw + 111616);
    float* rsb  = (float*)(smraw + 111744);

    int tid = threadIdx.x;
    int b = blockIdx.y;

    uint32_t xsu   = s2u(xs);
    uint32_t eW1Pu = s2u(eW1P);
    uint32_t eW2Pu = s2u(eW2P);
    uint32_t aHiU  = s2u(aHi);
    uint32_t aLoU  = s2u(aLo);

    // one-time prologue: packed W2, packed W1, first x tile
    for (int i = tid; i < 4096; i += 256) cpa16(eW2Pu + i * 16, g_ew2p + i * 8);
    for (int i = tid; i < 1024; i += 256) cpa16(eW1Pu + i * 16, g_ew1p + i * 8);
    {
        size_t base = ((size_t)b * E_ + (size_t)blockIdx.x * 32) * FIN_;
        if (tid < 192) cpa16(xsu + tid * 16, xin + base + tid * 4);
    }
    cpa_commit();
    if (tid < 128) {
        vb1[tid] = b1[tid];  vg1[tid] = g1[tid];  vbe1[tid] = be1[tid];
        vb2[tid] = b2[tid];  vg2[tid] = g2[tid];  vbe2[tid] = be2[tid];
        we1[tid] = watt1[128 + tid];
        we2[tid] = watt2[128 + tid];
    }
    cpa_wait0();
    __syncthreads();

    int warp = tid >> 5, lane = tid & 31;
    int gid = lane >> 2, tig = lane & 3;
    int arow = lane & 15;
    uint32_t ahalf = (lane >> 4) * 16;
    int m0  = (warp & 1) * 16;
    int wn  = warp >> 1;
    int n0w = wn * 32;
    int rA = m0 + gid, rB = rA + 8;

    int p = 0;
    for (int t = blockIdx.x; t < NTILE_; t += gridDim.x) {
        int e0 = t * 32;
        const float* xb = xs + p * 768;

        // convert x -> xHi/xLo bf16 split (stride 40; cols 24..31 zero)
        {
            int r = tid >> 3, q = (tid & 7) * 4;
            int o = r * 40 + q;
            if (q < FIN_) {
                float4 v = *(const float4*)&xb[r * FIN_ + q];
                __nv_bfloat162 h01 = __floats2bfloat162_rn(v.x, v.y);
                __nv_bfloat162 h23 = __floats2bfloat162_rn(v.z, v.w);
                __nv_bfloat162 l01 = __floats2bfloat162_rn(
                    v.x - __bfloat162float(h01.x), v.y - __bfloat162float(h01.y));
                __nv_bfloat162 l23 = __floats2bfloat162_rn(
                    v.z - __bfloat162float(h23.x), v.w - __bfloat162float(h23.y));
                *(__nv_bfloat162*)&xHi[o]     = h01;
                *(__nv_bfloat162*)&xHi[o + 2] = h23;
                *(__nv_bfloat162*)&xLo[o]     = l01;
                *(__nv_bfloat162*)&xLo[o + 2] = l23;
            } else {
                *(uint2*)&xHi[o] = make_uint2(0u, 0u);
                *(uint2*)&xLo[o] = make_uint2(0u, 0u);
            }
        }
        __syncthreads();

        // prefetch next x tile into buffer p^1 (xs[p] fully consumed by convert)
        {
            int tn = t + gridDim.x;
            if (tn < NTILE_) {
                size_t base = ((size_t)b * E_ + (size_t)tn * 32) * FIN_;
                if (tid < 192) cpa16(xsu + (p ^ 1) * 3072 + tid * 16, xin + base + tid * 4);
                cpa_commit();
            }
        }

        // GEMM1 (tensor): h[32][128] = x[32][24] @ W1. warp tile m16 x n32
        float acc1[4][4];
#pragma unroll
        for (int nf = 0; nf < 4; nf++)
#pragma unroll
            for (int j = 0; j < 4; j++) acc1[nf][j] = 0.f;

#pragma unroll
        for (int s = 0; s < 2; s++) {
            uint32_t ra = (m0 + arow) * 80 + s * 32 + ahalf;
            uint32_t xh[4], xl[4];
            LDMX4(xh, aHiU + ra);   // xHi aliased on aHi
            LDMX4(xl, aLoU + ra);
#pragma unroll
            for (int nf = 0; nf < 4; nf++) {
                int n = n0w + nf * 8 + gid;
                uint4 bb = *(const uint4*)&eW1P[((s * 128 + n) * 4 + tig) * 8];
                mma_bf16(acc1[nf], xh, bb.x, bb.y);
                mma_bf16(acc1[nf], xl, bb.x, bb.y);
                mma_bf16(acc1[nf], xh, bb.z, bb.w);
            }
        }

        // LN1 stats (cross-warp)
        {
            float s1 = 0.f, q1 = 0.f, s2 = 0.f, q2 = 0.f;
#pragma unroll
            for (int nf = 0; nf < 4; nf++) {
                int n = n0w + nf * 8 + 2 * tig;
                float vA0 = acc1[nf][0] + vb1[n];
                float vA1 = acc1[nf][1] + vb1[n + 1];
                float vB0 = acc1[nf][2] + vb1[n];
                float vB1 = acc1[nf][3] + vb1[n + 1];
                s1 += vA0 + vA1;  q1 += vA0 * vA0 + vA1 * vA1;
                s2 += vB0 + vB1;  q2 += vB0 * vB0 + vB1 * vB1;
            }
            s1 += __shfl_xor_sync(0xffffffffu, s1, 1);
            s1 += __shfl_xor_sync(0xffffffffu, s1, 2);
            q1 += __shfl_xor_sync(0xffffffffu, q1, 1);
            q1 += __shfl_xor_sync(0xffffffffu, q1, 2);
            s2 += __shfl_xor_sync(0xffffffffu, s2, 1);
            s2 += __shfl_xor_sync(0xffffffffu, s2, 2);
            q2 += __shfl_xor_sync(0xffffffffu, q2, 1);
            q2 += __shfl_xor_sync(0xffffffffu, q2, 2);
            if (tig == 0) {
                red[(rA * 4 + wn) * 4 + 0] = s1;
                red[(rA * 4 + wn) * 4 + 1] = q1;
                red[(rB * 4 + wn) * 4 + 0] = s2;
                red[(rB * 4 + wn) * 4 + 1] = q2;
            }
        }
        __syncthreads();
        if (tid < 32) {
            float S = 0.f, Q = 0.f;
#pragma unroll
            for (int w = 0; w < 4; w++) {
                S += red[(tid * 4 + w) * 4 + 0];
                Q += red[(tid * 4 + w) * 4 + 1];
            }
            float mu = S * (1.f / 128.f);
            float var = Q * (1.f / 128.f) - mu * mu;
            mub[tid] = mu;
            rsb[tid] = rsqrtf(var + 1e-5f);
        }
        __syncthreads();
        // gelu(LN1) -> aHi/aLo bf16 split (overwrites x frags; x is dead)
        {
            float muA = mub[rA], rsA = rsb[rA];
            float muB = mub[rB], rsB = rsb[rB];
#pragma unroll
            for (int nf = 0; nf < 4; nf++) {
                int n = n0w + nf * 8 + 2 * tig;
                float g0 = vg1[n], g1c = vg1[n + 1], e0c = vbe1[n], e1c = vbe1[n + 1];
                float yA0 = gelu_f((acc1[nf][0] + vb1[n]     - muA) * rsA * g0  + e0c);
                float yA1 = gelu_f((acc1[nf][1] + vb1[n + 1] - muA) * rsA * g1c + e1c);
                float yB0 = gelu_f((acc1[nf][2] + vb1[n]     - muB) * rsB * g0  + e0c);
                float yB1 = gelu_f((acc1[nf][3] + vb1[n + 1] - muB) * rsB * g1c + e1c);
                __nv_bfloat162 hA = __floats2bfloat162_rn(yA0, yA1);
                __nv_bfloat162 hB = __floats2bfloat162_rn(yB0, yB1);
                __nv_bfloat162 lA = __floats2bfloat162_rn(
                    yA0 - __bfloat162float(hA.x), yA1 - __bfloat162float(hA.y));
                __nv_bfloat162 lB = __floats2bfloat162_rn(
                    yB0 - __bfloat162float(hB.x), yB1 - __bfloat162float(hB.y));
                *(__nv_bfloat162*)&aHi[rA * 136 + n] = hA;
                *(__nv_bfloat162*)&aHi[rB * 136 + n] = hB;
                *(__nv_bfloat162*)&aLo[rA * 136 + n] = lA;
                *(__nv_bfloat162*)&aLo[rB * 136 + n] = lB;
            }
        }
        __syncthreads();   // aHi/aLo complete for all warps

        // GEMM2 (tensor): [32][128] = a[32][128] @ W2. warp tile m16 x n32
        float acc2[4][4];
#pragma unroll
        for (int nf = 0; nf < 4; nf++)
#pragma unroll
            for (int j = 0; j < 4; j++) acc2[nf][j] = 0.f;

#pragma unroll
        for (int s = 0; s < 8; s++) {
            uint32_t ra = (m0 + arow) * 272 + s * 32 + ahalf;
            uint32_t ah[4], al[4];
            LDMX4(ah, aHiU + ra);
            LDMX4(al, aLoU + ra);
#pragma unroll
            for (int nf = 0; nf < 4; nf++) {
                int n = n0w + nf * 8 + gid;
                uint4 bb = *(const uint4*)&eW2P[((s * 128 + n) * 4 + tig) * 8];
                mma_bf16(acc2[nf], ah, bb.x, bb.y);
                mma_bf16(acc2[nf], al, bb.x, bb.y);
                mma_bf16(acc2[nf], ah, bb.z, bb.w);
            }
        }

        // epilogue: +b2, LN2 (cross-warp), write emb (fp32 + bf16) + e_dots
        {
            float s1 = 0.f, q1 = 0.f, s2 = 0.f, q2 = 0.f;
#pragma unroll
            for (int nf = 0; nf < 4; nf++) {
                int n = n0w + nf * 8 + 2 * tig;
                float vA0 = acc2[nf][0] + vb2[n];
                float vA1 = acc2[nf][1] + vb2[n + 1];
                float vB0 = acc2[nf][2] + vb2[n];
                float vB1 = acc2[nf][3] + vb2[n + 1];
                s1 += vA0 + vA1;  q1 += vA0 * vA0 + vA1 * vA1;
                s2 += vB0 + vB1;  q2 += vB0 * vB0 + vB1 * vB1;
            }
            s1 += __shfl_xor_sync(0xffffffffu, s1, 1);
            s1 += __shfl_xor_sync(0xffffffffu, s1, 2);
            q1 += __shfl_xor_sync(0xffffffffu, q1, 1);
            q1 += __shfl_xor_sync(0xffffffffu, q1, 2);
            s2 += __shfl_xor_sync(0xffffffffu, s2, 1);
            s2 += __shfl_xor_sync(0xffffffffu, s2, 2);
            q2 += __shfl_xor_sync(0xffffffffu, q2, 1);
            q2 += __shfl_xor_sync(0xffffffffu, q2, 2);
            if (tig == 0) {
                red[(rA * 4 + wn) * 4 + 0] = s1;
                red[(rA * 4 + wn) * 4 + 1] = q1;
                red[(rB * 4 + wn) * 4 + 0] = s2;
                red[(rB * 4 + wn) * 4 + 1] = q2;
            }
        }
        __syncthreads();
        if (tid < 32) {
            float S = 0.f, Q = 0.f;
#pragma unroll
            for (int w = 0; w < 4; w++) {
                S += red[(tid * 4 + w) * 4 + 0];
                Q += red[(tid * 4 + w) * 4 + 1];
            }
            float mu = S * (1.f / 128.f);
            float var = Q * (1.f / 128.f) - mu * mu;
            mub[tid] = mu;
            rsb[tid] = rsqrtf(var + 1e-5f);
        }
        __syncthreads();
        {
            float muA = mub[rA], rsA = rsb[rA];
            float muB = mub[rB], rsB = rsb[rB];
            size_t rowA = (size_t)b * E_ + e0 + rA;
            size_t rowB = (size_t)b * E_ + e0 + rB;
            float p1A = 0.f, p2A = 0.f, p1B = 0.f, p2B = 0.f;
#pragma unroll
            for (int nf = 0; nf < 4; nf++) {
                int n = n0w + nf * 8 + 2 * tig;
                float g0 = vg2[n], g1c = vg2[n + 1], e0c = vbe2[n], e1c = vbe2[n + 1];
                float yA0 = (acc2[nf][0] + vb2[n]     - muA) * rsA * g0  + e0c;
                float yA1 = (acc2[nf][1] + vb2[n + 1] - muA) * rsA * g1c + e1c;
                float yB0 = (acc2[nf][2] + vb2[n]     - muB) * rsB * g0  + e0c;
                float yB1 = (acc2[nf][3] + vb2[n + 1] - muB) * rsB * g1c + e1c;
                *(float2*)&g_emb[rowA * D_ + n] = make_float2(yA0, yA1);
                *(float2*)&g_emb[rowB * D_ + n] = make_float2(yB0, yB1);
                *(__nv_bfloat162*)&g_embh[rowA * D_ + n] = __floats2bfloat162_rn(yA0, yA1);
                *(__nv_bfloat162*)&g_embh[rowB * D_ + n] = __floats2bfloat162_rn(yB0, yB1);
                p1A += yA0 * we1[n] + yA1 * we1[n + 1];
                p2A += yA0 * we2[n] + yA1 * we2[n + 1];
                p1B += yB0 * we1[n] + yB1 * we1[n + 1];
                p2B += yB0 * we2[n] + yB1 * we2[n + 1];
            }
            p1A += __shfl_xor_sync(0xffffffffu, p1A, 1);
            p1A += __shfl_xor_sync(0xffffffffu, p1A, 2);
            p2A += __shfl_xor_sync(0xffffffffu, p2A, 1);
            p2A += __shfl_xor_sync(0xffffffffu, p2A, 2);
            p1B += __shfl_xor_sync(0xffffffffu, p1B, 1);
            p1B += __shfl_xor_sync(0xffffffffu, p1B, 2);
            p2B += __shfl_xor_sync(0xffffffffu, p2B, 1);
            p2B += __shfl_xor_sync(0xffffffffu, p2B, 2);
            if (tig == 0) {
                red[(rA * 4 + wn) * 4 + 2] = p1A;
                red[(rA * 4 + wn) * 4 + 3] = p2A;
                red[(rB * 4 + wn) * 4 + 2] = p1B;
                red[(rB * 4 + wn) * 4 + 3] = p2B;
            }
        }
        __syncthreads();
        if (tid < 32) {
            float p1 = 0.f, p2 = 0.f;
#pragma unroll
            for (int w = 0; w < 4; w++) {
                p1 += red[(tid * 4 + w) * 4 + 2];
                p2 += red[(tid * 4 + w) * 4 + 3];
            }
            size_t row = (size_t)b * E_ + e0 + tid;
            g_edot[0][row] = p1;
            g_edot[1][row] = p2;
        }
        cpa_wait0();       // next x tile landed
        __syncthreads();   // red/aHi free for next tile
        p ^= 1;
    }
}

// ---------------- message passing (one warp per (batch, node)) ----------------
__global__ void mp_kernel(const float* __restrict__ watt,
                          const float* __restrict__ batt_p, int layer)
{
    int w = (blockIdx.x * blockDim.x + threadIdx.x) >> 5;
    int lane = threadIdx.x & 31;
    if (w >= B_ * N_) return;
    int b = w / N_, n = w % N_;

    const float* node_in = g_nodeA;                 // only read when layer==1
    float* node_out = (layer == 0) ? g_nodeA : g_nodeB;

    float batt = batt_p[0];
    float hd = 0.f;
    float4 cur = make_float4(0.f, 0.f, 0.f, 0.f);
    size_t nrow = ((size_t)b * N_ + n) * D_ + lane * 4;
    if (layer > 0) {
        cur = *(const float4*)&node_in[nrow];
        float4 wh = *(const float4*)&watt[lane * 4];
        float p = cur.x * wh.x + cur.y * wh.y + cur.z * wh.z + cur.w * wh.w;
        hd = wsum(p);
    }

    int start = g_off[n], end = g_off[n + 1];
    int deg = end - start;
    if (deg == 0) {                       // where(deg>0, new, node_b)
        *(float4*)&node_out[nrow] = cur;  // layer0: zeros; layer1: pass-through
        return;
    }

    const float* edot = &g_edot[layer][(size_t)b * E_];
    const __nv_bfloat16* embh = g_embh + (size_t)b * E_ * D_;

    float m = -1e30f;
    for (int i = start + lane; i < end; i += 32) {
        float s = hd + edot[g_adj[i]] + batt;
        s = (s > 0.f) ? s : 0.2f * s;
        m = fmaxf(m, s);
    }
    m = wmax(m);

    float den = 0.f;
    for (int i = start + lane; i < end; i += 32) {
        float s = hd + edot[g_adj[i]] + batt;
        s = (s > 0.f) ? s : 0.2f * s;
        den += expf(s - m);
    }
    den = wsum(den);

    float4 acc = make_float4(0.f, 0.f, 0.f, 0.f);
    int i = start;
    for (; i + 4 <= end; i += 4) {
        int ea = g_adj[i], eb = g_adj[i + 1], ec = g_adj[i + 2], ed = g_adj[i + 3];
        float sa = edot[ea], sb = edot[eb], sc = edot[ec], sd = edot[ed];
        uint2 ra = *(const uint2*)&embh[(size_t)ea * D_ + lane * 4];
        uint2 rb = *(const uint2*)&embh[(size_t)eb * D_ + lane * 4];
        uint2 rc = *(const uint2*)&embh[(size_t)ec * D_ + lane * 4];
        uint2 rd = *(const uint2*)&embh[(size_t)ed * D_ + lane * 4];
        sa = hd + sa + batt; sa = (sa > 0.f) ? sa : 0.2f * sa;
        sb = hd + sb + batt; sb = (sb > 0.f) ? sb : 0.2f * sb;
        sc = hd + sc + batt; sc = (sc > 0.f) ? sc : 0.2f * sc;
        sd = hd + sd + batt; sd = (sd > 0.f) ? sd : 0.2f * sd;
        float pa = expf(sa - m), pb = expf(sb - m);
        float pc = expf(sc - m), pd = expf(sd - m);
        float2 fa0 = __bfloat1622float2(*(__nv_bfloat162*)&ra.x);
        float2 fa1 = __bfloat1622float2(*(__nv_bfloat162*)&ra.y);
        float2 fb0 = __bfloat1622float2(*(__nv_bfloat162*)&rb.x);
        float2 fb1 = __bfloat1622float2(*(__nv_bfloat162*)&rb.y);
        float2 fc0 = __bfloat1622float2(*(__nv_bfloat162*)&rc.x);
        float2 fc1 = __bfloat1622float2(*(__nv_bfloat162*)&rc.y);
        float2 fd0 = __bfloat1622float2(*(__nv_bfloat162*)&rd.x);
        float2 fd1 = __bfloat1622float2(*(__nv_bfloat162*)&rd.y);
        acc.x = fmaf(pa, fa0.x, fmaf(pb, fb0.x, fmaf(pc, fc0.x, fmaf(pd, fd0.x, acc.x))));
        acc.y = fmaf(pa, fa0.y, fmaf(pb, fb0.y, fmaf(pc, fc0.y, fmaf(pd, fd0.y, acc.y))));
        acc.z = fmaf(pa, fa1.x, fmaf(pb, fb1.x, fmaf(pc, fc1.x, fmaf(pd, fd1.x, acc.z))));
        acc.w = fmaf(pa, fa1.y, fmaf(pb, fb1.y, fmaf(pc, fc1.y, fmaf(pd, fd1.y, acc.w))));
    }
    for (; i < end; i++) {
        int e = g_adj[i];
        float s = hd + edot[e] + batt;
        s = (s > 0.f) ? s : 0.2f * s;
        float p = expf(s - m);
        uint2 raw = *(const uint2*)&embh[(size_t)e * D_ + lane * 4];
        float2 f01 = __bfloat1622float2(*(__nv_bfloat162*)&raw.x);
        float2 f23 = __bfloat1622float2(*(__nv_bfloat162*)&raw.y);
        acc.x = fmaf(p, f01.x, acc.x);
        acc.y = fmaf(p, f01.y, acc.y);
        acc.z = fmaf(p, f23.x, acc.z);
        acc.w = fmaf(p, f23.y, acc.w);
    }
    float inv = 1.f / den;
    float4 outv;
    outv.x = gelu_f(acc.x * inv);
    outv.y = gelu_f(acc.y * inv);
    outv.z = gelu_f(acc.z * inv);
    outv.w = gelu_f(acc.w * inv);
    *(float4*)&node_out[nrow] = outv;
}

// ---------------- tensor-core decoder (bf16 split, depth-3 pipelines) ----------------
// 64 rows / 256 thr / 2 CTAs/SM.
// smem bytes:
//   G2 stages: 4 x 8KB @ 0..32768 (idle during G1)
//   catHi @32768 5120 | catLo @37888 5120
//   z1 region @43008..110592: during G1 holds 4 x 16KB W1 stages; after G1
//     epilogue holds z1Hi @43008 (33792) + z1Lo @76800 (33792)
//   b1s @110592 1024 | b2s @111616 512 | w3s @112128 512 | part @112640 512
//   sn @113152 256 | dn @113408 256  -> 113664
#define DEC_SMEM_BYTES 113664

__global__ void __launch_bounds__(256, 2) decoder_kernel(
    const float* __restrict__ b1, const float* __restrict__ b2,
    const float* __restrict__ w3, const float* __restrict__ b3,
    const int* __restrict__ src, const int* __restrict__ dst,
    float* __restrict__ out)
{
    extern __shared__ char smraw[];
    __nv_bfloat16* catHi = (__nv_bfloat16*)(smraw + 32768);
    __nv_bfloat16* catLo = (__nv_bfloat16*)(smraw + 37888);
    __nv_bfloat16* z1Hi  = (__nv_bfloat16*)(smraw + 43008);
    __nv_bfloat16* z1Lo  = (__nv_bfloat16*)(smraw + 76800);
    float* b1s  = (float*)(smraw + 110592);
    float* b2s  = (float*)(smraw + 111616);
    float* w3s  = (float*)(smraw + 112128);
    float* part = (float*)(smraw + 112640);
    int*   sn   = (int*)(smraw + 113152);
    int*   dn   = (int*)(smraw + 113408);

    int tid  = threadIdx.x;
    int lane = tid & 31;
    int warp = tid >> 5;
    int gid  = lane >> 2;
    int tig  = lane & 3;
    int b    = blockIdx.y;
    int e0   = blockIdx.x * 64;

    if (tid < 64) { sn[tid] = src[e0 + tid]; dn[tid] = dst[e0 + tid]; }
    b1s[tid] = b1[tid];
    if (tid < 128) { b2s[tid] = b2[tid]; w3s[tid] = w3[tid]; }

    const float* nodeb = g_nodeB + (size_t)b * N_ * D_;
    const float* embb  = g_emb   + (size_t)b * E_ * D_;

    uint32_t sbase  = s2u(smraw);
    uint32_t g1base = sbase + 43008;   // 4 x 16KB W1 stages in z1 region
    uint32_t catHiU = s2u(catHi);
    uint32_t catLoU = s2u(catLo);
    uint32_t z1HiU  = s2u(z1Hi);
    uint32_t z1LoU  = s2u(z1Lo);

    int arow  = lane & 15;
    uint32_t ahalf = (lane >> 4) * 16;

    // gather slots: this thread owns elements tid and tid+256 of each 512-slot chunk
    int r0g = tid >> 3,          q0g = (tid & 7) * 4;
    int r1g = (tid + 256) >> 3,  q1g = (tid & 7) * 4;

    // ---------- GEMM1: warp tile 32x64; 4x16KB stages, depth-3 ----------
    int m0 = (warp & 1) * 32;
    int n0 = (warp >> 1) * 64;

    float acc[2][8][4];
#pragma unroll
    for (int mf = 0; mf < 2; mf++)
#pragma unroll
        for (int nf = 0; nf < 8; nf++)
#pragma unroll
            for (int j = 0; j < 4; j++) acc[mf][nf][j] = 0.f;

    // prologue: stage W1 slices 0,1,2 (3 groups in flight)
#pragma unroll
    for (int k = 0; k < 3; k++) {
        for (int i = tid; i < 1024; i += 256)
            cpa16(g1base + k * 16384 + i * 16, g_w1p + k * 8192 + i * 8);
        cpa_commit();
    }
    __syncthreads();   // sn/dn visible for gather preloads

    // preload gather chunk 0 into registers
    float4 gv0, gv1;
    gv0 = *(const float4*)&nodeb[(size_t)sn[r0g] * D_ + q0g];
    gv1 = *(const float4*)&nodeb[(size_t)sn[r1g] * D_ + q1g];

    for (int s = 0; s < 24; s++) {
        if (s <= 21) cpa_wait2();
        else if (s == 22) cpa_wait1();
        else cpa_wait0();
        __syncthreads();   // stage s visible; all compute(s-1) done
        if ((s & 1) == 0) {
            if (s + 3 < 24) {   // stage s+3 into buf (s+3)&3 (reader s-1 done)
                const __nv_bfloat16* pS = g_w1p + (size_t)(s + 3) * 8192;
                uint32_t dS = g1base + ((s + 3) & 3) * 16384;
#pragma unroll
                for (int i = tid; i < 1024; i += 256)
                    cpa16(dS + i * 16, pS + i * 8);
                cpa_commit();
            }
            // store preloaded gather chunk s>>1 (bf16 hi/lo split)
            {
                __nv_bfloat162 h01 = __floats2bfloat162_rn(gv0.x, gv0.y);
                __nv_bfloat162 h23 = __floats2bfloat162_rn(gv0.z, gv0.w);
                __nv_bfloat162 l01 = __floats2bfloat162_rn(
                    gv0.x - __bfloat162float(h01.x), gv0.y - __bfloat162float(h01.y));
                __nv_bfloat162 l23 = __floats2bfloat162_rn(
                    gv0.z - __bfloat162float(h23.x), gv0.w - __bfloat162float(h23.y));
                int o = r0g * 40 + q0g;
                *(__nv_bfloat162*)&catHi[o]     = h01;
                *(__nv_bfloat162*)&catHi[o + 2] = h23;
                *(__nv_bfloat162*)&catLo[o]     = l01;
                *(__nv_bfloat162*)&catLo[o + 2] = l23;
                h01 = __floats2bfloat162_rn(gv1.x, gv1.y);
                h23 = __floats2bfloat162_rn(gv1.z, gv1.w);
                l01 = __floats2bfloat162_rn(
                    gv1.x - __bfloat162float(h01.x), gv1.y - __bfloat162float(h01.y));
                l23 = __floats2bfloat162_rn(
                    gv1.z - __bfloat162float(h23.x), gv1.w - __bfloat162float(h23.y));
                o = r1g * 40 + q1g;
                *(__nv_bfloat162*)&catHi[o]     = h01;
                *(__nv_bfloat162*)&catHi[o + 2] = h23;
                *(__nv_bfloat162*)&catLo[o]     = l01;
                *(__nv_bfloat162*)&catLo[o + 2] = l23;
            }
            __syncthreads();   // cat stores visible
        } else {
            if (s + 3 < 24) {
                const __nv_bfloat16* pS = g_w1p + (size_t)(s + 3) * 8192;
                uint32_t dS = g1base + ((s + 3) & 3) * 16384;
#pragma unroll
                for (int i = tid; i < 1024; i += 256)
                    cpa16(dS + i * 16, pS + i * 8);
                cpa_commit();
            }
            // preload NEXT gather chunk (latency hidden under compute)
            int c = (s >> 1) + 1;
            if (c < 12) {
                int kc = c * 32;
                if (kc < 128) {
                    gv0 = *(const float4*)&nodeb[(size_t)sn[r0g] * D_ + kc + q0g];
                    gv1 = *(const float4*)&nodeb[(size_t)sn[r1g] * D_ + kc + q1g];
                } else if (kc < 256) {
                    gv0 = *(const float4*)&nodeb[(size_t)dn[r0g] * D_ + kc - 128 + q0g];
                    gv1 = *(const float4*)&nodeb[(size_t)dn[r1g] * D_ + kc - 128 + q1g];
                } else {
                    gv0 = *(const float4*)&embb[(size_t)(e0 + r0g) * D_ + kc - 256 + q0g];
                    gv1 = *(const float4*)&embb[(size_t)(e0 + r1g) * D_ + kc - 256 + q1g];
                }
            }
        }
        // compute slice s
        const __nv_bfloat16* st = (const __nv_bfloat16*)(smraw + 43008 + (s & 3) * 16384);
        uint32_t ab = (s & 1) * 32 + ahalf;
        uint32_t ah[2][4], al[2][4];
#pragma unroll
        for (int mf = 0; mf < 2; mf++) {
            uint32_t ra = (m0 + mf * 16 + arow) * 80 + ab;
            LDMX4(ah[mf], catHiU + ra);
            LDMX4(al[mf], catLoU + ra);
        }
#pragma unroll
        for (int nf = 0; nf < 8; nf++) {
            int n = n0 + nf * 8 + gid;
            uint4 bb = *(const uint4*)&st[(n * 4 + tig) * 8];
#pragma unroll
            for (int mf = 0; mf < 2; mf++) {
                mma_bf16(acc[mf][nf], ah[mf], bb.x, bb.y);
                mma_bf16(acc[mf][nf], al[mf], bb.x, bb.y);
                mma_bf16(acc[mf][nf], ah[mf], bb.z, bb.w);
            }
        }
    }

    // issue G2 stages 0,1,2 (region 0..24576 untouched during G1; overlaps epilogue)
#pragma unroll
    for (int k = 0; k < 3; k++) {
        for (int i = tid; i < 512; i += 256)
            cpa16(sbase + k * 8192 + i * 16, g_w2p + k * 4096 + i * 8);
        cpa_commit();
    }
    __syncthreads();   // all warps past G1 compute before z1 overwrites stage bufs

    // GEMM1 epilogue: bias + gelu -> z1 (bf16 hi/lo, own-warp tile)
#pragma unroll
    for (int mf = 0; mf < 2; mf++) {
        int rlo = m0 + mf * 16 + gid;
#pragma unroll
        for (int nf = 0; nf < 8; nf++) {
            int c = n0 + nf * 8 + 2 * tig;
            float v0 = gelu_f(acc[mf][nf][0] + b1s[c]);
            float v1 = gelu_f(acc[mf][nf][1] + b1s[c + 1]);
            float v2 = gelu_f(acc[mf][nf][2] + b1s[c]);
            float v3 = gelu_f(acc[mf][nf][3] + b1s[c + 1]);
            __nv_bfloat162 h01 = __floats2bfloat162_rn(v0, v1);
            __nv_bfloat162 h23 = __floats2bfloat162_rn(v2, v3);
            __nv_bfloat162 l01 = __floats2bfloat162_rn(
                v0 - __bfloat162float(h01.x), v1 - __bfloat162float(h01.y));
            __nv_bfloat162 l23 = __floats2bfloat162_rn(
                v2 - __bfloat162float(h23.x), v3 - __bfloat162float(h23.y));
            *(__nv_bfloat162*)&z1Hi[rlo * 264 + c]       = h01;
            *(__nv_bfloat162*)&z1Hi[(rlo + 8) * 264 + c] = h23;
            *(__nv_bfloat162*)&z1Lo[rlo * 264 + c]       = l01;
            *(__nv_bfloat162*)&z1Lo[(rlo + 8) * 264 + c] = l23;
        }
    }

    // ---------- GEMM2: warp tile 16x64; 4x8KB stages, depth-3 ----------
    int m20 = (warp & 3) * 16;
    int n20 = (warp >> 2) * 64;

    float acc2[8][4];
#pragma unroll
    for (int nf = 0; nf < 8; nf++)
#pragma unroll
        for (int j = 0; j < 4; j++) acc2[nf][j] = 0.f;

    for (int s = 0; s < 16; s++) {
        if (s <= 13) cpa_wait2();
        else if (s == 14) cpa_wait1();
        else cpa_wait0();
        __syncthreads();   // stage s + z1 writes (s=0) visible; compute(s-1) done
        if (s + 3 < 16) {   // stage s+3 into buf (s+3)&3 (reader s-1 done)
            const __nv_bfloat16* pS = g_w2p + (size_t)(s + 3) * 4096;
            uint32_t dS = sbase + ((s + 3) & 3) * 8192;
#pragma unroll
            for (int i = tid; i < 512; i += 256)
                cpa16(dS + i * 16, pS + i * 8);
            cpa_commit();
        }
        const __nv_bfloat16* st = (const __nv_bfloat16*)(smraw + (s & 3) * 8192);
        uint32_t ra = (m20 + arow) * 528 + s * 32 + ahalf;
        uint32_t ah[4], al[4];
        LDMX4(ah, z1HiU + ra);
        LDMX4(al, z1LoU + ra);
#pragma unroll
        for (int nf = 0; nf < 8; nf++) {
            int n = n20 + nf * 8 + gid;
            uint4 bb = *(const uint4*)&st[(n * 4 + tig) * 8];
            mma_bf16(acc2[nf], ah, bb.x, bb.y);
            mma_bf16(acc2[nf], al, bb.x, bb.y);
            mma_bf16(acc2[nf], ah, bb.z, bb.w);
        }
    }

    // epilogue: gelu(z2 + b2) . w3, reduce over n
    float plo = 0.f, phi = 0.f;
#pragma unroll
    for (int nf = 0; nf < 8; nf++) {
        int c = n20 + nf * 8 + 2 * tig;
        float u0 = gelu_f(acc2[nf][0] + b2s[c]) * w3s[c];
        float u1 = gelu_f(acc2[nf][1] + b2s[c + 1]) * w3s[c + 1];
        float u2 = gelu_f(acc2[nf][2] + b2s[c]) * w3s[c];
        float u3 = gelu_f(acc2[nf][3] + b2s[c + 1]) * w3s[c + 1];
        plo += u0 + u1;
        phi += u2 + u3;
    }
    plo += __shfl_xor_sync(0xffffffffu, plo, 1);
    plo += __shfl_xor_sync(0xffffffffu, plo, 2);
    phi += __shfl_xor_sync(0xffffffffu, phi, 1);
    phi += __shfl_xor_sync(0xffffffffu, phi, 2);
    __syncthreads();
    if (tig == 0) {
        part[(warp >> 2) * 64 + m20 + gid]     = plo;
        part[(warp >> 2) * 64 + m20 + gid + 8] = phi;
    }
    __syncthreads();
    if (tid < 64) {
        out[(size_t)b * E_ + e0 + tid] = part[tid] + part[64 + tid] + b3[0];
    }
}

// ---------------- launch ----------------
extern "C" void kernel_launch(void* const* d_in, const int* in_sizes, int n_in,
                              void* d_out, int out_size)
{
    const float* edge_features = (const float*)d_in[0];
    const float* enc_w1  = (const float*)d_in[1];
    const float* enc_b1  = (const float*)d_in[2];
    const float* enc_g1  = (const float*)d_in[3];
    const float* enc_be1 = (const float*)d_in[4];
    const float* enc_w2  = (const float*)d_in[5];
    const float* enc_b2  = (const float*)d_in[6];
    const float* enc_g2  = (const float*)d_in[7];
    const float* enc_be2 = (const float*)d_in[8];
    const float* watt1   = (const float*)d_in[9];
    const float* batt1   = (const float*)d_in[10];
    const float* watt2   = (const float*)d_in[11];
    const float* batt2   = (const float*)d_in[12];
    const float* dec_w1  = (const float*)d_in[13];
    const float* dec_b1  = (const float*)d_in[14];
    const float* dec_w2  = (const float*)d_in[15];
    const float* dec_b2  = (const float*)d_in[16];
    const float* dec_w3  = (const float*)d_in[17];
    const float* dec_b3  = (const float*)d_in[18];
    const int*   src     = (const int*)d_in[19];
    const int*   dst     = (const int*)d_in[20];
    float* out = (float*)d_out;

    cudaFuncSetAttribute(encoder_kernel, cudaFuncAttributeMaxDynamicSharedMemorySize,
                         ENC_SMEM_BYTES);
    cudaFuncSetAttribute(decoder_kernel, cudaFuncAttributeMaxDynamicSharedMemorySize,
                         DEC_SMEM_BYTES);

    // pack (+ fused cnt zero)
    pack_weights_kernel<<<148, 256>>>(dec_w1, dec_w2, enc_w2, enc_w1);
    // CSR count + scan
    count_kernel<<<(P2E_ + 255) / 256, 256>>>(src, dst);
    scan_kernel<<<1, 1024>>>();

    // persistent fused encoder (4th launch -> gets the ncu profile)
    encoder_kernel<<<dim3(148, B_), 256, ENC_SMEM_BYTES>>>(
        edge_features, enc_b1, enc_g1, enc_be1,
        enc_b2, enc_g2, enc_be2, watt1, watt2);

    // CSR fill (needs scan; independent of encoder)
    fill_kernel<<<(P2E_ + 255) / 256, 256>>>(src, dst);

    // message passing: layer 1 (node_in = 0), layer 2
    int mp_blocks = (B_ * N_ + 7) / 8;   // 8 warps/block
    mp_kernel<<<mp_blocks, 256>>>(watt1, batt1, 0);
    mp_kernel<<<mp_blocks, 256>>>(watt2, batt2, 1);

    // tensor-core decoder MLP (depth-3 pipelines)
    decoder_kernel<<<dim3(E_ / 64, B_), 256, DEC_SMEM_BYTES>>>(
        dec_b1, dec_b2, dec_w3, dec_b3, src, dst, out);
}

// round 12
// speedup vs baseline: 1.0623x; 1.0623x over previous
#include <cuda_runtime.h>
#include <cuda_bf16.h>
#include <cstdint>
#include <cstddef>
#include <math.h>

// Problem constants (fixed dataset)
#define B_   2
#define E_   160000
#define N_   10000
#define FIN_ 24
#define D_   128
#define P2E_ (2 * E_)
#define NTILE_ (E_ / 32)   // 5000

// ---------------- scratch (static __device__, no allocations) ----------------
__device__ float g_emb[(size_t)B_ * E_ * D_];     // edge embeddings [B][E][128] fp32
__device__ __nv_bfloat16 g_embh[(size_t)B_ * E_ * D_]; // bf16 mirror for MP gather
__device__ float g_edot[2][(size_t)B_ * E_];      // per-layer e_pair . watt[128:256]
__device__ float g_nodeA[(size_t)B_ * N_ * D_];   // node emb after layer 1
__device__ float g_nodeB[(size_t)B_ * N_ * D_];   // node emb after layer 2
__device__ int   g_cnt[N_];
__device__ int   g_cur[N_];
__device__ int   g_off[N_ + 1];
__device__ int   g_adj[P2E_];
// bf16 packed weights, m16n8k16 B-fragment order, hi|lo INTERLEAVED per (n,tig):
//   group g=(s*N+n)*4+t holds 8 bf16: [hi j=0..3 | lo j=0..3], k = s*16+2t+(j&1)+((j>>1)<<3)
__device__ __align__(16) __nv_bfloat16 g_w1p[384 * 256 * 2];
__device__ __align__(16) __nv_bfloat16 g_w2p[256 * 128 * 2];
__device__ __align__(16) __nv_bfloat16 g_ew2p[128 * 128 * 2];
__device__ __align__(16) __nv_bfloat16 g_ew1p[32 * 128 * 2];   // enc W1, k padded 24->32

// ---------------- helpers ----------------
__device__ __forceinline__ float gelu_f(float x) {
    return 0.5f * x * (1.0f + erff(x * 0.70710678118654752f));
}
__device__ __forceinline__ float wsum(float v) {
#pragma unroll
    for (int o = 16; o; o >>= 1) v += __shfl_xor_sync(0xffffffffu, v, o);
    return v;
}
__device__ __forceinline__ float wmax(float v) {
#pragma unroll
    for (int o = 16; o; o >>= 1) v = fmaxf(v, __shfl_xor_sync(0xffffffffu, v, o));
    return v;
}
__device__ __forceinline__ uint32_t s2u(const void* p) {
    return (uint32_t)__cvta_generic_to_shared(p);
}
__device__ __forceinline__ void cpa16(uint32_t dst, const void* src) {
    asm volatile("cp.async.cg.shared.global [%0], [%1], 16;" :: "r"(dst), "l"(src));
}
__device__ __forceinline__ void cpa_commit() {
    asm volatile("cp.async.commit_group;" ::: "memory");
}
__device__ __forceinline__ void cpa_wait0() {
    asm volatile("cp.async.wait_group 0;" ::: "memory");
}
#define LDMX4(r, addr) \
    asm volatile("ldmatrix.sync.aligned.m8n8.x4.shared.b16 {%0,%1,%2,%3}, [%4];" \
        : "=r"((r)[0]), "=r"((r)[1]), "=r"((r)[2]), "=r"((r)[3]) : "r"(addr))

__device__ __forceinline__ void mma_bf16(float* c, const uint32_t* a,
                                         uint32_t b0, uint32_t b1) {
    asm volatile(
        "mma.sync.aligned.m16n8k16.row.col.f32.bf16.bf16.f32 "
        "{%0,%1,%2,%3},{%4,%5,%6,%7},{%8,%9},{%0,%1,%2,%3};"
        : "+f"(c[0]), "+f"(c[1]), "+f"(c[2]), "+f"(c[3])
        : "r"(a[0]), "r"(a[1]), "r"(a[2]), "r"(a[3]), "r"(b0), "r"(b1));
}

// ---------------- weight pack prep (interleaved hi|lo fragment groups) ----------------
__device__ __forceinline__ void pack_group(__nv_bfloat16* dst, const float* src,
                                           int N, int gi, int Kmax) {
    int t = gi & 3;
    int n = (gi >> 2) % N;
    int s = gi / (4 * N);
#pragma unroll
    for (int j = 0; j < 4; j++) {
        int k = s * 16 + 2 * t + (j & 1) + ((j >> 1) << 3);
        float x = (k < Kmax) ? src[k * N + n] : 0.f;
        __nv_bfloat16 h = __float2bfloat16_rn(x);
        dst[gi * 8 + j]     = h;
        dst[gi * 8 + 4 + j] = __float2bfloat16_rn(x - __bfloat162float(h));
    }
}

__global__ void pack_weights_kernel(const float* __restrict__ w1,
                                    const float* __restrict__ w2,
                                    const float* __restrict__ ew2,
                                    const float* __restrict__ ew1) {
    int gi = blockIdx.x * blockDim.x + threadIdx.x;
    if (gi < N_) g_cnt[gi] = 0;   // fused zero_cnt
    if (gi < 24576)       pack_group(g_w1p, w1, 256, gi, 384);            // dec W1 384x256
    else if (gi < 32768)  pack_group(g_w2p, w2, 128, gi - 24576, 256);    // dec W2 256x128
    else if (gi < 36864)  pack_group(g_ew2p, ew2, 128, gi - 32768, 128);  // enc W2 128x128
    else if (gi < 37888)  pack_group(g_ew1p, ew1, 128, gi - 36864, 24);   // enc W1 24x128 (pad 32)
}

// ---------------- CSR build ----------------
__global__ void count_kernel(const int* __restrict__ src, const int* __restrict__ dst) {
    int idx = blockIdx.x * blockDim.x + threadIdx.x;
    if (idx >= P2E_) return;
    int node = (idx < E_) ? src[idx] : dst[idx - E_];
    atomicAdd(&g_cnt[node], 1);
}

__global__ void scan_kernel() {
    __shared__ int ss[1024];
    int t = threadIdx.x;
    int base = t * 10;                  // 1024*10 >= N_
    int s = 0;
#pragma unroll
    for (int i = 0; i < 10; i++) {
        int idx = base + i;
        if (idx < N_) s += g_cnt[idx];
    }
    ss[t] = s;
    __syncthreads();
    for (int off = 1; off < 1024; off <<= 1) {
        int v = (t >= off) ? ss[t - off] : 0;
        __syncthreads();
        ss[t] += v;
        __syncthreads();
    }
    int run = (t > 0) ? ss[t - 1] : 0;
#pragma unroll
    for (int i = 0; i < 10; i++) {
        int idx = base + i;
        if (idx < N_) {
            g_off[idx] = run;
            run += g_cnt[idx];
            g_cur[idx] = 0;
        }
    }
    if (t == 1023) g_off[N_] = ss[1023];
}

__global__ void fill_kernel(const int* __restrict__ src, const int* __restrict__ dst) {
    int idx = blockIdx.x * blockDim.x + threadIdx.x;
    if (idx >= P2E_) return;
    int node = (idx < E_) ? src[idx] : dst[idx - E_];
    int e    = (idx < E_) ? idx : idx - E_;
    int pos = g_off[node] + atomicAdd(&g_cur[node], 1);
    g_adj[pos] = e;
}

// ---------------- persistent fused edge encoder (both GEMMs tensorized) ----------------
#define ENC_SMEM_BYTES 111872
__global__ void __launch_bounds__(256, 2) encoder_kernel(
    const float* __restrict__ xin,
    const float* __restrict__ b1,
    const float* __restrict__ g1, const float* __restrict__ be1,
    const float* __restrict__ b2,
    const float* __restrict__ g2, const float* __restrict__ be2,
    const float* __restrict__ watt1, const float* __restrict__ watt2)
{
    extern __shared__ char smraw[];
    float* xs = (float*)(smraw);             // two 768-float buffers
    __nv_bfloat16* eW1P = (__nv_bfloat16*)(smraw + 6144);
    __nv_bfloat16* eW2P = (__nv_bfloat16*)(smraw + 22528);
    __nv_bfloat16* aHi  = (__nv_bfloat16*)(smraw + 88064);
    __nv_bfloat16* aLo  = (__nv_bfloat16*)(smraw + 96768);
    __nv_bfloat16* xHi  = aHi;   // alias: x frags dead before gelu writes land
    __nv_bfloat16* xLo  = aLo;
    float* vb1  = (float*)(smraw + 105472);
    float* vg1  = (float*)(smraw + 105984);
    float* vbe1 = (float*)(smraw + 106496);
    float* vb2  = (float*)(smraw + 107008);
    float* vg2  = (float*)(smraw + 107520);
    float* vbe2 = (float*)(smraw + 108032);
    float* we1  = (float*)(smraw + 108544);
    float* we2  = (float*)(smraw + 109056);
    float* red  = (float*)(smraw + 109568);
    float* mub  = (float*)(smraw + 111616);
    float* rsb  = (float*)(smraw + 111744);

    int tid = threadIdx.x;
    int b = blockIdx.y;

    uint32_t xsu   = s2u(xs);
    uint32_t eW1Pu = s2u(eW1P);
    uint32_t eW2Pu = s2u(eW2P);
    uint32_t aHiU  = s2u(aHi);
    uint32_t aLoU  = s2u(aLo);

    // one-time prologue: packed W2, packed W1, first x tile
    for (int i = tid; i < 4096; i += 256) cpa16(eW2Pu + i * 16, g_ew2p + i * 8);
    for (int i = tid; i < 1024; i += 256) cpa16(eW1Pu + i * 16, g_ew1p + i * 8);
    {
        size_t base = ((size_t)b * E_ + (size_t)blockIdx.x * 32) * FIN_;
        if (tid < 192) cpa16(xsu + tid * 16, xin + base + tid * 4);
    }
    cpa_commit();
    if (tid < 128) {
        vb1[tid] = b1[tid];  vg1[tid] = g1[tid];  vbe1[tid] = be1[tid];
        vb2[tid] = b2[tid];  vg2[tid] = g2[tid];  vbe2[tid] = be2[tid];
        we1[tid] = watt1[128 + tid];
        we2[tid] = watt2[128 + tid];
    }
    cpa_wait0();
    __syncthreads();

    int warp = tid >> 5, lane = tid & 31;
    int gid = lane >> 2, tig = lane & 3;
    int arow = lane & 15;
    uint32_t ahalf = (lane >> 4) * 16;
    int m0  = (warp & 1) * 16;
    int wn  = warp >> 1;
    int n0w = wn * 32;
    int rA = m0 + gid, rB = rA + 8;

    int p = 0;
    for (int t = blockIdx.x; t < NTILE_; t += gridDim.x) {
        int e0 = t * 32;
        const float* xb = xs + p * 768;

        // convert x -> xHi/xLo bf16 split (stride 40; cols 24..31 zero)
        {
            int r = tid >> 3, q = (tid & 7) * 4;
            int o = r * 40 + q;
            if (q < FIN_) {
                float4 v = *(const float4*)&xb[r * FIN_ + q];
                __nv_bfloat162 h01 = __floats2bfloat162_rn(v.x, v.y);
                __nv_bfloat162 h23 = __floats2bfloat162_rn(v.z, v.w);
                __nv_bfloat162 l01 = __floats2bfloat162_rn(
                    v.x - __bfloat162float(h01.x), v.y - __bfloat162float(h01.y));
                __nv_bfloat162 l23 = __floats2bfloat162_rn(
                    v.z - __bfloat162float(h23.x), v.w - __bfloat162float(h23.y));
                *(__nv_bfloat162*)&xHi[o]     = h01;
                *(__nv_bfloat162*)&xHi[o + 2] = h23;
                *(__nv_bfloat162*)&xLo[o]     = l01;
                *(__nv_bfloat162*)&xLo[o + 2] = l23;
            } else {
                *(uint2*)&xHi[o] = make_uint2(0u, 0u);
                *(uint2*)&xLo[o] = make_uint2(0u, 0u);
            }
        }
        __syncthreads();

        // prefetch next x tile into buffer p^1 (xs[p] fully consumed by convert)
        {
            int tn = t + gridDim.x;
            if (tn < NTILE_) {
                size_t base = ((size_t)b * E_ + (size_t)tn * 32) * FIN_;
                if (tid < 192) cpa16(xsu + (p ^ 1) * 3072 + tid * 16, xin + base + tid * 4);
                cpa_commit();
            }
        }

        // GEMM1 (tensor): h[32][128] = x[32][24] @ W1. warp tile m16 x n32
        float acc1[4][4];
#pragma unroll
        for (int nf = 0; nf < 4; nf++)
#pragma unroll
            for (int j = 0; j < 4; j++) acc1[nf][j] = 0.f;

#pragma unroll
        for (int s = 0; s < 2; s++) {
            uint32_t ra = (m0 + arow) * 80 + s * 32 + ahalf;
            uint32_t xh[4], xl[4];
            LDMX4(xh, aHiU + ra);   // xHi aliased on aHi
            LDMX4(xl, aLoU + ra);
#pragma unroll
            for (int nf = 0; nf < 4; nf++) {
                int n = n0w + nf * 8 + gid;
                uint4 bb = *(const uint4*)&eW1P[((s * 128 + n) * 4 + tig) * 8];
                mma_bf16(acc1[nf], xh, bb.x, bb.y);
                mma_bf16(acc1[nf], xl, bb.x, bb.y);
                mma_bf16(acc1[nf], xh, bb.z, bb.w);
            }
        }

        // LN1 stats (cross-warp)
        {
            float s1 = 0.f, q1 = 0.f, s2 = 0.f, q2 = 0.f;
#pragma unroll
            for (int nf = 0; nf < 4; nf++) {
                int n = n0w + nf * 8 + 2 * tig;
                float vA0 = acc1[nf][0] + vb1[n];
                float vA1 = acc1[nf][1] + vb1[n + 1];
                float vB0 = acc1[nf][2] + vb1[n];
                float vB1 = acc1[nf][3] + vb1[n + 1];
                s1 += vA0 + vA1;  q1 += vA0 * vA0 + vA1 * vA1;
                s2 += vB0 + vB1;  q2 += vB0 * vB0 + vB1 * vB1;
            }
            s1 += __shfl_xor_sync(0xffffffffu, s1, 1);
            s1 += __shfl_xor_sync(0xffffffffu, s1, 2);
            q1 += __shfl_xor_sync(0xffffffffu, q1, 1);
            q1 += __shfl_xor_sync(0xffffffffu, q1, 2);
            s2 += __shfl_xor_sync(0xffffffffu, s2, 1);
            s2 += __shfl_xor_sync(0xffffffffu, s2, 2);
            q2 += __shfl_xor_sync(0xffffffffu, q2, 1);
            q2 += __shfl_xor_sync(0xffffffffu, q2, 2);
            if (tig == 0) {
                red[(rA * 4 + wn) * 4 + 0] = s1;
                red[(rA * 4 + wn) * 4 + 1] = q1;
                red[(rB * 4 + wn) * 4 + 0] = s2;
                red[(rB * 4 + wn) * 4 + 1] = q2;
            }
        }
        __syncthreads();
        if (tid < 32) {
            float S = 0.f, Q = 0.f;
#pragma unroll
            for (int w = 0; w < 4; w++) {
                S += red[(tid * 4 + w) * 4 + 0];
                Q += red[(tid * 4 + w) * 4 + 1];
            }
            float mu = S * (1.f / 128.f);
            float var = Q * (1.f / 128.f) - mu * mu;
            mub[tid] = mu;
            rsb[tid] = rsqrtf(var + 1e-5f);
        }
        __syncthreads();
        // gelu(LN1) -> aHi/aLo bf16 split (overwrites x frags; x is dead)
        {
            float muA = mub[rA], rsA = rsb[rA];
            float muB = mub[rB], rsB = rsb[rB];
#pragma unroll
            for (int nf = 0; nf < 4; nf++) {
                int n = n0w + nf * 8 + 2 * tig;
                float g0 = vg1[n], g1c = vg1[n + 1], e0c = vbe1[n], e1c = vbe1[n + 1];
                float yA0 = gelu_f((acc1[nf][0] + vb1[n]     - muA) * rsA * g0  + e0c);
                float yA1 = gelu_f((acc1[nf][1] + vb1[n + 1] - muA) * rsA * g1c + e1c);
                float yB0 = gelu_f((acc1[nf][2] + vb1[n]     - muB) * rsB * g0  + e0c);
                float yB1 = gelu_f((acc1[nf][3] + vb1[n + 1] - muB) * rsB * g1c + e1c);
                __nv_bfloat162 hA = __floats2bfloat162_rn(yA0, yA1);
                __nv_bfloat162 hB = __floats2bfloat162_rn(yB0, yB1);
                __nv_bfloat162 lA = __floats2bfloat162_rn(
                    yA0 - __bfloat162float(hA.x), yA1 - __bfloat162float(hA.y));
                __nv_bfloat162 lB = __floats2bfloat162_rn(
                    yB0 - __bfloat162float(hB.x), yB1 - __bfloat162float(hB.y));
                *(__nv_bfloat162*)&aHi[rA * 136 + n] = hA;
                *(__nv_bfloat162*)&aHi[rB * 136 + n] = hB;
                *(__nv_bfloat162*)&aLo[rA * 136 + n] = lA;
                *(__nv_bfloat162*)&aLo[rB * 136 + n] = lB;
            }
        }
        __syncthreads();   // aHi/aLo complete for all warps

        // GEMM2 (tensor): [32][128] = a[32][128] @ W2. warp tile m16 x n32
        float acc2[4][4];
#pragma unroll
        for (int nf = 0; nf < 4; nf++)
#pragma unroll
            for (int j = 0; j < 4; j++) acc2[nf][j] = 0.f;

#pragma unroll
        for (int s = 0; s < 8; s++) {
            uint32_t ra = (m0 + arow) * 272 + s * 32 + ahalf;
            uint32_t ah[4], al[4];
            LDMX4(ah, aHiU + ra);
            LDMX4(al, aLoU + ra);
#pragma unroll
            for (int nf = 0; nf < 4; nf++) {
                int n = n0w + nf * 8 + gid;
                uint4 bb = *(const uint4*)&eW2P[((s * 128 + n) * 4 + tig) * 8];
                mma_bf16(acc2[nf], ah, bb.x, bb.y);
                mma_bf16(acc2[nf], al, bb.x, bb.y);
                mma_bf16(acc2[nf], ah, bb.z, bb.w);
            }
        }

        // epilogue: +b2, LN2 (cross-warp), write emb (fp32 + bf16) + e_dots
        {
            float s1 = 0.f, q1 = 0.f, s2 = 0.f, q2 = 0.f;
#pragma unroll
            for (int nf = 0; nf < 4; nf++) {
                int n = n0w + nf * 8 + 2 * tig;
                float vA0 = acc2[nf][0] + vb2[n];
                float vA1 = acc2[nf][1] + vb2[n + 1];
                float vB0 = acc2[nf][2] + vb2[n];
                float vB1 = acc2[nf][3] + vb2[n + 1];
                s1 += vA0 + vA1;  q1 += vA0 * vA0 + vA1 * vA1;
                s2 += vB0 + vB1;  q2 += vB0 * vB0 + vB1 * vB1;
            }
            s1 += __shfl_xor_sync(0xffffffffu, s1, 1);
            s1 += __shfl_xor_sync(0xffffffffu, s1, 2);
            q1 += __shfl_xor_sync(0xffffffffu, q1, 1);
            q1 += __shfl_xor_sync(0xffffffffu, q1, 2);
            s2 += __shfl_xor_sync(0xffffffffu, s2, 1);
            s2 += __shfl_xor_sync(0xffffffffu, s2, 2);
            q2 += __shfl_xor_sync(0xffffffffu, q2, 1);
            q2 += __shfl_xor_sync(0xffffffffu, q2, 2);
            if (tig == 0) {
                red[(rA * 4 + wn) * 4 + 0] = s1;
                red[(rA * 4 + wn) * 4 + 1] = q1;
                red[(rB * 4 + wn) * 4 + 0] = s2;
                red[(rB * 4 + wn) * 4 + 1] = q2;
            }
        }
        __syncthreads();
        if (tid < 32) {
            float S = 0.f, Q = 0.f;
#pragma unroll
            for (int w = 0; w < 4; w++) {
                S += red[(tid * 4 + w) * 4 + 0];
                Q += red[(tid * 4 + w) * 4 + 1];
            }
            float mu = S * (1.f / 128.f);
            float var = Q * (1.f / 128.f) - mu * mu;
            mub[tid] = mu;
            rsb[tid] = rsqrtf(var + 1e-5f);
        }
        __syncthreads();
        {
            float muA = mub[rA], rsA = rsb[rA];
            float muB = mub[rB], rsB = rsb[rB];
            size_t rowA = (size_t)b * E_ + e0 + rA;
            size_t rowB = (size_t)b * E_ + e0 + rB;
            float p1A = 0.f, p2A = 0.f, p1B = 0.f, p2B = 0.f;
#pragma unroll
            for (int nf = 0; nf < 4; nf++) {
                int n = n0w + nf * 8 + 2 * tig;
                float g0 = vg2[n], g1c = vg2[n + 1], e0c = vbe2[n], e1c = vbe2[n + 1];
                float yA0 = (acc2[nf][0] + vb2[n]     - muA) * rsA * g0  + e0c;
                float yA1 = (acc2[nf][1] + vb2[n + 1] - muA) * rsA * g1c + e1c;
                float yB0 = (acc2[nf][2] + vb2[n]     - muB) * rsB * g0  + e0c;
                float yB1 = (acc2[nf][3] + vb2[n + 1] - muB) * rsB * g1c + e1c;
                *(float2*)&g_emb[rowA * D_ + n] = make_float2(yA0, yA1);
                *(float2*)&g_emb[rowB * D_ + n] = make_float2(yB0, yB1);
                *(__nv_bfloat162*)&g_embh[rowA * D_ + n] = __floats2bfloat162_rn(yA0, yA1);
                *(__nv_bfloat162*)&g_embh[rowB * D_ + n] = __floats2bfloat162_rn(yB0, yB1);
                p1A += yA0 * we1[n] + yA1 * we1[n + 1];
                p2A += yA0 * we2[n] + yA1 * we2[n + 1];
                p1B += yB0 * we1[n] + yB1 * we1[n + 1];
                p2B += yB0 * we2[n] + yB1 * we2[n + 1];
            }
            p1A += __shfl_xor_sync(0xffffffffu, p1A, 1);
            p1A += __shfl_xor_sync(0xffffffffu, p1A, 2);
            p2A += __shfl_xor_sync(0xffffffffu, p2A, 1);
            p2A += __shfl_xor_sync(0xffffffffu, p2A, 2);
            p1B += __shfl_xor_sync(0xffffffffu, p1B, 1);
            p1B += __shfl_xor_sync(0xffffffffu, p1B, 2);
            p2B += __shfl_xor_sync(0xffffffffu, p2B, 1);
            p2B += __shfl_xor_sync(0xffffffffu, p2B, 2);
            if (tig == 0) {
                red[(rA * 4 + wn) * 4 + 2] = p1A;
                red[(rA * 4 + wn) * 4 + 3] = p2A;
                red[(rB * 4 + wn) * 4 + 2] = p1B;
                red[(rB * 4 + wn) * 4 + 3] = p2B;
            }
        }
        __syncthreads();
        if (tid < 32) {
            float p1 = 0.f, p2 = 0.f;
#pragma unroll
            for (int w = 0; w < 4; w++) {
                p1 += red[(tid * 4 + w) * 4 + 2];
                p2 += red[(tid * 4 + w) * 4 + 3];
            }
            size_t row = (size_t)b * E_ + e0 + tid;
            g_edot[0][row] = p1;
            g_edot[1][row] = p2;
        }
        cpa_wait0();       // next x tile landed
        __syncthreads();   // red/aHi free for next tile
        p ^= 1;
    }
}

// ---------------- message passing (one warp per (batch, node)) ----------------
__global__ void mp_kernel(const float* __restrict__ watt,
                          const float* __restrict__ batt_p, int layer)
{
    int w = (blockIdx.x * blockDim.x + threadIdx.x) >> 5;
    int lane = threadIdx.x & 31;
    if (w >= B_ * N_) return;
    int b = w / N_, n = w % N_;

    const float* node_in = g_nodeA;                 // only read when layer==1
    float* node_out = (layer == 0) ? g_nodeA : g_nodeB;

    float batt = batt_p[0];
    float hd = 0.f;
    float4 cur = make_float4(0.f, 0.f, 0.f, 0.f);
    size_t nrow = ((size_t)b * N_ + n) * D_ + lane * 4;
    if (layer > 0) {
        cur = *(const float4*)&node_in[nrow];
        float4 wh = *(const float4*)&watt[lane * 4];
        float p = cur.x * wh.x + cur.y * wh.y + cur.z * wh.z + cur.w * wh.w;
        hd = wsum(p);
    }

    int start = g_off[n], end = g_off[n + 1];
    int deg = end - start;
    if (deg == 0) {                       // where(deg>0, new, node_b)
        *(float4*)&node_out[nrow] = cur;  // layer0: zeros; layer1: pass-through
        return;
    }

    const float* edot = &g_edot[layer][(size_t)b * E_];
    const __nv_bfloat16* embh = g_embh + (size_t)b * E_ * D_;

    float m = -1e30f;
    for (int i = start + lane; i < end; i += 32) {
        float s = hd + edot[g_adj[i]] + batt;
        s = (s > 0.f) ? s : 0.2f * s;
        m = fmaxf(m, s);
    }
    m = wmax(m);

    float den = 0.f;
    for (int i = start + lane; i < end; i += 32) {
        float s = hd + edot[g_adj[i]] + batt;
        s = (s > 0.f) ? s : 0.2f * s;
        den += expf(s - m);
    }
    den = wsum(den);

    float4 acc = make_float4(0.f, 0.f, 0.f, 0.f);
    int i = start;
    for (; i + 4 <= end; i += 4) {
        int ea = g_adj[i], eb = g_adj[i + 1], ec = g_adj[i + 2], ed = g_adj[i + 3];
        float sa = edot[ea], sb = edot[eb], sc = edot[ec], sd = edot[ed];
        uint2 ra = *(const uint2*)&embh[(size_t)ea * D_ + lane * 4];
        uint2 rb = *(const uint2*)&embh[(size_t)eb * D_ + lane * 4];
        uint2 rc = *(const uint2*)&embh[(size_t)ec * D_ + lane * 4];
        uint2 rd = *(const uint2*)&embh[(size_t)ed * D_ + lane * 4];
        sa = hd + sa + batt; sa = (sa > 0.f) ? sa : 0.2f * sa;
        sb = hd + sb + batt; sb = (sb > 0.f) ? sb : 0.2f * sb;
        sc = hd + sc + batt; sc = (sc > 0.f) ? sc : 0.2f * sc;
        sd = hd + sd + batt; sd = (sd > 0.f) ? sd : 0.2f * sd;
        float pa = expf(sa - m), pb = expf(sb - m);
        float pc = expf(sc - m), pd = expf(sd - m);
        float2 fa0 = __bfloat1622float2(*(__nv_bfloat162*)&ra.x);
        float2 fa1 = __bfloat1622float2(*(__nv_bfloat162*)&ra.y);
        float2 fb0 = __bfloat1622float2(*(__nv_bfloat162*)&rb.x);
        float2 fb1 = __bfloat1622float2(*(__nv_bfloat162*)&rb.y);
        float2 fc0 = __bfloat1622float2(*(__nv_bfloat162*)&rc.x);
        float2 fc1 = __bfloat1622float2(*(__nv_bfloat162*)&rc.y);
        float2 fd0 = __bfloat1622float2(*(__nv_bfloat162*)&rd.x);
        float2 fd1 = __bfloat1622float2(*(__nv_bfloat162*)&rd.y);
        acc.x = fmaf(pa, fa0.x, fmaf(pb, fb0.x, fmaf(pc, fc0.x, fmaf(pd, fd0.x, acc.x))));
        acc.y = fmaf(pa, fa0.y, fmaf(pb, fb0.y, fmaf(pc, fc0.y, fmaf(pd, fd0.y, acc.y))));
        acc.z = fmaf(pa, fa1.x, fmaf(pb, fb1.x, fmaf(pc, fc1.x, fmaf(pd, fd1.x, acc.z))));
        acc.w = fmaf(pa, fa1.y, fmaf(pb, fb1.y, fmaf(pc, fc1.y, fmaf(pd, fd1.y, acc.w))));
    }
    for (; i < end; i++) {
        int e = g_adj[i];
        float s = hd + edot[e] + batt;
        s = (s > 0.f) ? s : 0.2f * s;
        float p = expf(s - m);
        uint2 raw = *(const uint2*)&embh[(size_t)e * D_ + lane * 4];
        float2 f01 = __bfloat1622float2(*(__nv_bfloat162*)&raw.x);
        float2 f23 = __bfloat1622float2(*(__nv_bfloat162*)&raw.y);
        acc.x = fmaf(p, f01.x, acc.x);
        acc.y = fmaf(p, f01.y, acc.y);
        acc.z = fmaf(p, f23.x, acc.z);
        acc.w = fmaf(p, f23.y, acc.w);
    }
    float inv = 1.f / den;
    float4 outv;
    outv.x = gelu_f(acc.x * inv);
    outv.y = gelu_f(acc.y * inv);
    outv.z = gelu_f(acc.z * inv);
    outv.w = gelu_f(acc.w * inv);
    *(float4*)&node_out[nrow] = outv;
}

// ---------------- tensor-core decoder (bf16 split, 2-slice stages) ----------------
// 64 rows / 256 thr / 2 CTAs/SM. Stages hold TWO k16 slices -> half the
// wait/sync events. G1 stages 2x32KB in z1 region; G2 stages 2x16KB at base.
// Register gather preload as in R10.
// smem bytes:
//   G2 stages @0, @16384 (2 x 16KB; idle during G1)
//   catHi @32768 5120 | catLo @37888 5120
//   z1 region @43008..110592: during G1 holds 2 x 32KB W1 stages; after G1
//     epilogue holds z1Hi @43008 (33792) + z1Lo @76800 (33792)
//   b1s @110592 1024 | b2s @111616 512 | w3s @112128 512 | part @112640 512
//   sn @113152 256 | dn @113408 256  -> 113664
#define DEC_SMEM_BYTES 113664

__global__ void __launch_bounds__(256, 2) decoder_kernel(
    const float* __restrict__ b1, const float* __restrict__ b2,
    const float* __restrict__ w3, const float* __restrict__ b3,
    const int* __restrict__ src, const int* __restrict__ dst,
    float* __restrict__ out)
{
    extern __shared__ char smraw[];
    __nv_bfloat16* catHi = (__nv_bfloat16*)(smraw + 32768);
    __nv_bfloat16* catLo = (__nv_bfloat16*)(smraw + 37888);
    __nv_bfloat16* z1Hi  = (__nv_bfloat16*)(smraw + 43008);
    __nv_bfloat16* z1Lo  = (__nv_bfloat16*)(smraw + 76800);
    float* b1s  = (float*)(smraw + 110592);
    float* b2s  = (float*)(smraw + 111616);
    float* w3s  = (float*)(smraw + 112128);
    float* part = (float*)(smraw + 112640);
    int*   sn   = (int*)(smraw + 113152);
    int*   dn   = (int*)(smraw + 113408);

    int tid  = threadIdx.x;
    int lane = tid & 31;
    int warp = tid >> 5;
    int gid  = lane >> 2;
    int tig  = lane & 3;
    int b    = blockIdx.y;
    int e0   = blockIdx.x * 64;

    if (tid < 64) { sn[tid] = src[e0 + tid]; dn[tid] = dst[e0 + tid]; }
    b1s[tid] = b1[tid];
    if (tid < 128) { b2s[tid] = b2[tid]; w3s[tid] = w3[tid]; }

    const float* nodeb = g_nodeB + (size_t)b * N_ * D_;
    const float* embb  = g_emb   + (size_t)b * E_ * D_;

    uint32_t sbase  = s2u(smraw);
    uint32_t g1base = sbase + 43008;   // 2 x 32KB W1 stages in z1 region
    uint32_t catHiU = s2u(catHi);
    uint32_t catLoU = s2u(catLo);
    uint32_t z1HiU  = s2u(z1Hi);
    uint32_t z1LoU  = s2u(z1Lo);

    int arow  = lane & 15;
    uint32_t ahalf = (lane >> 4) * 16;

    // gather slots: this thread owns elements tid and tid+256 of each 512-slot chunk
    int r0g = tid >> 3,          q0g = (tid & 7) * 4;
    int r1g = (tid + 256) >> 3,  q1g = (tid & 7) * 4;

    // ---------- GEMM1: warp tile 32x64; 2x32KB stages (2 slices each) ----------
    int m0 = (warp & 1) * 32;
    int n0 = (warp >> 1) * 64;

    float acc[2][8][4];
#pragma unroll
    for (int mf = 0; mf < 2; mf++)
#pragma unroll
        for (int nf = 0; nf < 8; nf++)
#pragma unroll
            for (int j = 0; j < 4; j++) acc[mf][nf][j] = 0.f;

    // prologue: stage 0 (slices 0,1 = 32KB)
    {
#pragma unroll
        for (int i = tid; i < 2048; i += 256)
            cpa16(g1base + i * 16, g_w1p + i * 8);
        cpa_commit();
    }
    __syncthreads();   // sn/dn visible for gather preloads

    // preload gather chunk 0 into registers
    float4 gv0, gv1;
    gv0 = *(const float4*)&nodeb[(size_t)sn[r0g] * D_ + q0g];
    gv1 = *(const float4*)&nodeb[(size_t)sn[r1g] * D_ + q1g];

    for (int it = 0; it < 12; it++) {
        cpa_wait0();
        __syncthreads();   // stage it visible; all compute(it-1) done
        // issue stage it+1 into buf (it+1)&1 (its last reader was compute it-1)
        if (it + 1 < 12) {
            const __nv_bfloat16* pS = g_w1p + (size_t)(it + 1) * 16384;
            uint32_t dS = g1base + ((it + 1) & 1) * 32768;
#pragma unroll
            for (int i = tid; i < 2048; i += 256)
                cpa16(dS + i * 16, pS + i * 8);
            cpa_commit();
        }
        // store preloaded gather chunk it (bf16 hi/lo split)
        {
            __nv_bfloat162 h01 = __floats2bfloat162_rn(gv0.x, gv0.y);
            __nv_bfloat162 h23 = __floats2bfloat162_rn(gv0.z, gv0.w);
            __nv_bfloat162 l01 = __floats2bfloat162_rn(
                gv0.x - __bfloat162float(h01.x), gv0.y - __bfloat162float(h01.y));
            __nv_bfloat162 l23 = __floats2bfloat162_rn(
                gv0.z - __bfloat162float(h23.x), gv0.w - __bfloat162float(h23.y));
            int o = r0g * 40 + q0g;
            *(__nv_bfloat162*)&catHi[o]     = h01;
            *(__nv_bfloat162*)&catHi[o + 2] = h23;
            *(__nv_bfloat162*)&catLo[o]     = l01;
            *(__nv_bfloat162*)&catLo[o + 2] = l23;
            h01 = __floats2bfloat162_rn(gv1.x, gv1.y);
            h23 = __floats2bfloat162_rn(gv1.z, gv1.w);
            l01 = __floats2bfloat162_rn(
                gv1.x - __bfloat162float(h01.x), gv1.y - __bfloat162float(h01.y));
            l23 = __floats2bfloat162_rn(
                gv1.z - __bfloat162float(h23.x), gv1.w - __bfloat162float(h23.y));
            o = r1g * 40 + q1g;
            *(__nv_bfloat162*)&catHi[o]     = h01;
            *(__nv_bfloat162*)&catHi[o + 2] = h23;
            *(__nv_bfloat162*)&catLo[o]     = l01;
            *(__nv_bfloat162*)&catLo[o + 2] = l23;
        }
        __syncthreads();   // cat stores visible
        // preload NEXT gather chunk (latency hidden under compute)
        {
            int c = it + 1;
            if (c < 12) {
                int kc = c * 32;
                if (kc < 128) {
                    gv0 = *(const float4*)&nodeb[(size_t)sn[r0g] * D_ + kc + q0g];
                    gv1 = *(const float4*)&nodeb[(size_t)sn[r1g] * D_ + kc + q1g];
                } else if (kc < 256) {
                    gv0 = *(const float4*)&nodeb[(size_t)dn[r0g] * D_ + kc - 128 + q0g];
                    gv1 = *(const float4*)&nodeb[(size_t)dn[r1g] * D_ + kc - 128 + q1g];
                } else {
                    gv0 = *(const float4*)&embb[(size_t)(e0 + r0g) * D_ + kc - 256 + q0g];
                    gv1 = *(const float4*)&embb[(size_t)(e0 + r1g) * D_ + kc - 256 + q1g];
                }
            }
        }
        // compute slices 2it, 2it+1 from stage buf it&1
        uint32_t stB = g1base + (it & 1) * 32768;
#pragma unroll
        for (int sl = 0; sl < 2; sl++) {
            const __nv_bfloat16* st =
                (const __nv_bfloat16*)(smraw + 43008 + (it & 1) * 32768 + sl * 16384);
            uint32_t ab = sl * 32 + ahalf;
            uint32_t ah[2][4], al[2][4];
#pragma unroll
            for (int mf = 0; mf < 2; mf++) {
                uint32_t ra = (m0 + mf * 16 + arow) * 80 + ab;
                LDMX4(ah[mf], catHiU + ra);
                LDMX4(al[mf], catLoU + ra);
            }
#pragma unroll
            for (int nf = 0; nf < 8; nf++) {
                int n = n0 + nf * 8 + gid;
                uint4 bb = *(const uint4*)&st[(n * 4 + tig) * 8];
#pragma unroll
                for (int mf = 0; mf < 2; mf++) {
                    mma_bf16(acc[mf][nf], ah[mf], bb.x, bb.y);
                    mma_bf16(acc[mf][nf], al[mf], bb.x, bb.y);
                    mma_bf16(acc[mf][nf], ah[mf], bb.z, bb.w);
                }
            }
        }
        (void)stB;
    }

    // issue G2 stage 0 (slices 0,1 -> 16KB at base; region idle during G1)
    {
#pragma unroll
        for (int i = tid; i < 1024; i += 256)
            cpa16(sbase + i * 16, g_w2p + i * 8);
        cpa_commit();
    }
    __syncthreads();   // all warps past G1 compute before z1 overwrites stage bufs

    // GEMM1 epilogue: bias + gelu -> z1 (bf16 hi/lo, own-warp tile)
#pragma unroll
    for (int mf = 0; mf < 2; mf++) {
        int rlo = m0 + mf * 16 + gid;
#pragma unroll
        for (int nf = 0; nf < 8; nf++) {
            int c = n0 + nf * 8 + 2 * tig;
            float v0 = gelu_f(acc[mf][nf][0] + b1s[c]);
            float v1 = gelu_f(acc[mf][nf][1] + b1s[c + 1]);
            float v2 = gelu_f(acc[mf][nf][2] + b1s[c]);
            float v3 = gelu_f(acc[mf][nf][3] + b1s[c + 1]);
            __nv_bfloat162 h01 = __floats2bfloat162_rn(v0, v1);
            __nv_bfloat162 h23 = __floats2bfloat162_rn(v2, v3);
            __nv_bfloat162 l01 = __floats2bfloat162_rn(
                v0 - __bfloat162float(h01.x), v1 - __bfloat162float(h01.y));
            __nv_bfloat162 l23 = __floats2bfloat162_rn(
                v2 - __bfloat162float(h23.x), v3 - __bfloat162float(h23.y));
            *(__nv_bfloat162*)&z1Hi[rlo * 264 + c]       = h01;
            *(__nv_bfloat162*)&z1Hi[(rlo + 8) * 264 + c] = h23;
            *(__nv_bfloat162*)&z1Lo[rlo * 264 + c]       = l01;
            *(__nv_bfloat162*)&z1Lo[(rlo + 8) * 264 + c] = l23;
        }
    }

    // ---------- GEMM2: warp tile 16x64; 2x16KB stages (2 slices each) ----------
    int m20 = (warp & 3) * 16;
    int n20 = (warp >> 2) * 64;

    float acc2[8][4];
#pragma unroll
    for (int nf = 0; nf < 8; nf++)
#pragma unroll
        for (int j = 0; j < 4; j++) acc2[nf][j] = 0.f;

    for (int it = 0; it < 8; it++) {
        cpa_wait0();
        __syncthreads();   // stage it + z1 writes (it=0) visible; compute(it-1) done
        if (it + 1 < 8) {
            const __nv_bfloat16* pS = g_w2p + (size_t)(it + 1) * 8192;
            uint32_t dS = sbase + ((it + 1) & 1) * 16384;
#pragma unroll
            for (int i = tid; i < 1024; i += 256)
                cpa16(dS + i * 16, pS + i * 8);
            cpa_commit();
        }
#pragma unroll
        for (int sl = 0; sl < 2; sl++) {
            const __nv_bfloat16* st =
                (const __nv_bfloat16*)(smraw + (it & 1) * 16384 + sl * 8192);
            int s = 2 * it + sl;
            uint32_t ra = (m20 + arow) * 528 + s * 32 + ahalf;
            uint32_t ah[4], al[4];
            LDMX4(ah, z1HiU + ra);
            LDMX4(al, z1LoU + ra);
#pragma unroll
            for (int nf = 0; nf < 8; nf++) {
                int n = n20 + nf * 8 + gid;
                uint4 bb = *(const uint4*)&st[(n * 4 + tig) * 8];
                mma_bf16(acc2[nf], ah, bb.x, bb.y);
                mma_bf16(acc2[nf], al, bb.x, bb.y);
                mma_bf16(acc2[nf], ah, bb.z, bb.w);
            }
        }
    }

    // epilogue: gelu(z2 + b2) . w3, reduce over n
    float plo = 0.f, phi = 0.f;
#pragma unroll
    for (int nf = 0; nf < 8; nf++) {
        int c = n20 + nf * 8 + 2 * tig;
        float u0 = gelu_f(acc2[nf][0] + b2s[c]) * w3s[c];
        float u1 = gelu_f(acc2[nf][1] + b2s[c + 1]) * w3s[c + 1];
        float u2 = gelu_f(acc2[nf][2] + b2s[c]) * w3s[c];
        float u3 = gelu_f(acc2[nf][3] + b2s[c + 1]) * w3s[c + 1];
        plo += u0 + u1;
        phi += u2 + u3;
    }
    plo += __shfl_xor_sync(0xffffffffu, plo, 1);
    plo += __shfl_xor_sync(0xffffffffu, plo, 2);
    phi += __shfl_xor_sync(0xffffffffu, phi, 1);
    phi += __shfl_xor_sync(0xffffffffu, phi, 2);
    __syncthreads();
    if (tig == 0) {
        part[(warp >> 2) * 64 + m20 + gid]     = plo;
        part[(warp >> 2) * 64 + m20 + gid + 8] = phi;
    }
    __syncthreads();
    if (tid < 64) {
        out[(size_t)b * E_ + e0 + tid] = part[tid] + part[64 + tid] + b3[0];
    }
}

// ---------------- launch ----------------
extern "C" void kernel_launch(void* const* d_in, const int* in_sizes, int n_in,
                              void* d_out, int out_size)
{
    const float* edge_features = (const float*)d_in[0];
    const float* enc_w1  = (const float*)d_in[1];
    const float* enc_b1  = (const float*)d_in[2];
    const float* enc_g1  = (const float*)d_in[3];
    const float* enc_be1 = (const float*)d_in[4];
    const float* enc_w2  = (const float*)d_in[5];
    const float* enc_b2  = (const float*)d_in[6];
    const float* enc_g2  = (const float*)d_in[7];
    const float* enc_be2 = (const float*)d_in[8];
    const float* watt1   = (const float*)d_in[9];
    const float* batt1   = (const float*)d_in[10];
    const float* watt2   = (const float*)d_in[11];
    const float* batt2   = (const float*)d_in[12];
    const float* dec_w1  = (const float*)d_in[13];
    const float* dec_b1  = (const float*)d_in[14];
    const float* dec_w2  = (const float*)d_in[15];
    const float* dec_b2  = (const float*)d_in[16];
    const float* dec_w3  = (const float*)d_in[17];
    const float* dec_b3  = (const float*)d_in[18];
    const int*   src     = (const int*)d_in[19];
    const int*   dst     = (const int*)d_in[20];
    float* out = (float*)d_out;

    cudaFuncSetAttribute(encoder_kernel, cudaFuncAttributeMaxDynamicSharedMemorySize,
                         ENC_SMEM_BYTES);
    cudaFuncSetAttribute(decoder_kernel, cudaFuncAttributeMaxDynamicSharedMemorySize,
                         DEC_SMEM_BYTES);

    // pack (+ fused cnt zero)
    pack_weights_kernel<<<148, 256>>>(dec_w1, dec_w2, enc_w2, enc_w1);
    // CSR count + scan
    count_kernel<<<(P2E_ + 255) / 256, 256>>>(src, dst);
    scan_kernel<<<1, 1024>>>();

    // persistent fused encoder (4th launch -> gets the ncu profile)
    encoder_kernel<<<dim3(148, B_), 256, ENC_SMEM_BYTES>>>(
        edge_features, enc_b1, enc_g1, enc_be1,
        enc_b2, enc_g2, enc_be2, watt1, watt2);

    // CSR fill (needs scan; independent of encoder)
    fill_kernel<<<(P2E_ + 255) / 256, 256>>>(src, dst);

    // message passing: layer 1 (node_in = 0), layer 2
    int mp_blocks = (B_ * N_ + 7) / 8;   // 8 warps/block
    mp_kernel<<<mp_blocks, 256>>>(watt1, batt1, 0);
    mp_kernel<<<mp_blocks, 256>>>(watt2, batt2, 1);

    // tensor-core decoder MLP (2-slice stages, halved barrier count)
    decoder_kernel<<<dim3(E_ / 64, B_), 256, DEC_SMEM_BYTES>>>(
        dec_b1, dec_b2, dec_w3, dec_b3, src, dst, out);
}